// round 2
// baseline (speedup 1.0000x reference)
#include <cuda_runtime.h>
#include <math.h>

// Problem constants (fixed by the reference)
#define BATCH   2
#define SEQ     2048
#define DMODEL  1024
#define NHEADS  16
#define HDIM    64
#define ROWS    (BATCH * SEQ)        // 4096
#define QKVCOLS (3 * DMODEL)         // 3072

// Scratch (static device globals — allocation-free per harness rules)
__device__ float g_qkv[(size_t)ROWS * QKVCOLS];   // 50 MB
__device__ float g_att[(size_t)ROWS * DMODEL];    // 16 MB

// ---------------------------------------------------------------------------
// SGEMM: C[M,N] = A[M,K] @ B[K,N] + bias[N]
// Block tile 128x128, K-tile 8, 256 threads, 8x8 register tile per thread.
// Register-staged prefetch: global loads for tile k+1 issued before the
// FMA loop over tile k, hiding DRAM/L2 latency behind compute.
// M,N,K all multiples of tile sizes for this problem (no bounds checks).
// ---------------------------------------------------------------------------
__global__ __launch_bounds__(256, 2)
void sgemm_bias_kernel(const float* __restrict__ A,
                       const float* __restrict__ Bm,
                       const float* __restrict__ bias,
                       float* __restrict__ C,
                       int M, int N, int K)
{
    const int BM = 128, BN = 128, BK = 8, TM = 8, TN = 8;
    __shared__ float As[BK][BM];
    __shared__ float Bs[BK][BN];

    const int tid  = threadIdx.x;          // 0..255
    const int tx   = tid & 15;             // 0..15
    const int ty   = tid >> 4;             // 0..15
    const int row0 = blockIdx.y * BM;
    const int col0 = blockIdx.x * BN;

    float acc[TM][TN];
#pragma unroll
    for (int i = 0; i < TM; i++)
#pragma unroll
        for (int j = 0; j < TN; j++) acc[i][j] = 0.0f;

    // A loader: 128 rows x 8 cols = 1024 floats -> one float4 per thread
    const int a_row = tid >> 1;            // 0..127
    const int a_col = (tid & 1) * 4;       // 0 or 4
    // B loader: 8 rows x 128 cols -> one float4 per thread
    const int b_row = tid >> 5;            // 0..7
    const int b_col = (tid & 31) * 4;      // 0..124

    const float* Aptr = A + (size_t)(row0 + a_row) * K + a_col;
    const float* Bptr = Bm + (size_t)b_row * N + col0 + b_col;

    // Preload first K-tile into registers
    float4 av = *(const float4*)(Aptr);
    float4 bv = *(const float4*)(Bptr);

    for (int k0 = 0; k0 < K; k0 += BK) {
        // Commit staged registers to shared
        As[a_col + 0][a_row] = av.x;
        As[a_col + 1][a_row] = av.y;
        As[a_col + 2][a_row] = av.z;
        As[a_col + 3][a_row] = av.w;
        *(float4*)&Bs[b_row][b_col] = bv;
        __syncthreads();

        // Prefetch next K-tile (overlaps with FMA loop below)
        const int k1 = k0 + BK;
        if (k1 < K) {
            av = *(const float4*)(Aptr + k1);
            bv = *(const float4*)(Bptr + (size_t)k1 * N);
        }

#pragma unroll
        for (int kk = 0; kk < BK; kk++) {
            float ra[TM], rb[TN];
#pragma unroll
            for (int i = 0; i < TM; i++) ra[i] = As[kk][ty * TM + i];
#pragma unroll
            for (int j = 0; j < TN; j++) rb[j] = Bs[kk][tx * TN + j];
#pragma unroll
            for (int i = 0; i < TM; i++)
#pragma unroll
                for (int j = 0; j < TN; j++)
                    acc[i][j] = fmaf(ra[i], rb[j], acc[i][j]);
        }
        __syncthreads();
    }

    // Epilogue with bias, vectorized stores
#pragma unroll
    for (int i = 0; i < TM; i++) {
        const int row = row0 + ty * TM + i;
        float* crow = C + (size_t)row * N + col0 + tx * TN;
        const float* brow = bias + col0 + tx * TN;
#pragma unroll
        for (int j4 = 0; j4 < TN; j4 += 4) {
            float4 v;
            v.x = acc[i][j4 + 0] + brow[j4 + 0];
            v.y = acc[i][j4 + 1] + brow[j4 + 1];
            v.z = acc[i][j4 + 2] + brow[j4 + 2];
            v.w = acc[i][j4 + 3] + brow[j4 + 3];
            *(float4*)&crow[j4] = v;
        }
    }
}

// ---------------------------------------------------------------------------
// Flash attention (fp32, causal), one head-batch per blockIdx.y,
// 64 query rows per block, 64-key tiles, online softmax.
// Dynamic smem: Q[64][65], K[64][65], S[64][65], V[64][64], m/l/alpha[64]x3
// ---------------------------------------------------------------------------
#define BQ 64
#define BK_T 64
#define QPAD 65
#define SMEM_FLOATS (3 * BQ * QPAD + BQ * HDIM + 3 * BQ)
#define SMEM_BYTES (SMEM_FLOATS * 4)

__global__ __launch_bounds__(256, 3)
void flash_attn_kernel(const float* __restrict__ qkv, float* __restrict__ att)
{
    extern __shared__ float sm[];
    float* sQ = sm;                       // [64][65]
    float* sK = sQ + BQ * QPAD;           // [64][65]
    float* sS = sK + BQ * QPAD;           // [64][65]
    float* sV = sS + BQ * QPAD;           // [64][64]
    float* sM = sV + BQ * HDIM;           // [64]
    float* sL = sM + BQ;                  // [64]
    float* sA = sL + BQ;                  // [64]

    const int tid  = threadIdx.x;         // 0..255
    const int tx   = tid & 15;
    const int ty   = tid >> 4;
    const int warp = tid >> 5;            // 0..7
    const int lane = tid & 31;

    const int bh = blockIdx.y;
    const int b  = bh / NHEADS;
    const int h  = bh % NHEADS;
    // Reverse q-tile order so heaviest (largest q0) causal blocks start first
    const int qt = gridDim.x - 1 - blockIdx.x;
    const int q0 = qt * BQ;

    const size_t rowbase = (size_t)b * SEQ;
    const int qcol = h * HDIM;            // q col offset in qkv row
    const int kcol = DMODEL + h * HDIM;
    const int vcol = 2 * DMODEL + h * HDIM;

    // Load Q tile: 64 rows x 64 cols (1024 float4s / 256 threads)
    for (int i = tid; i < BQ * (HDIM / 4); i += 256) {
        const int r  = i >> 4;            // 0..63
        const int c4 = (i & 15) * 4;      // 0..60
        float4 v = *(const float4*)&qkv[(rowbase + q0 + r) * QKVCOLS + qcol + c4];
        sQ[r * QPAD + c4 + 0] = v.x;
        sQ[r * QPAD + c4 + 1] = v.y;
        sQ[r * QPAD + c4 + 2] = v.z;
        sQ[r * QPAD + c4 + 3] = v.w;
    }
    if (tid < BQ) { sM[tid] = -1e30f; sL[tid] = 0.0f; }

    float acc[4][4];
#pragma unroll
    for (int i = 0; i < 4; i++)
#pragma unroll
        for (int j = 0; j < 4; j++) acc[i][j] = 0.0f;

    __syncthreads();

    const int n_kt = q0 / BK_T + 1;       // causal: key tiles 0..n_kt-1
    for (int kt = 0; kt < n_kt; kt++) {
        const int k0 = kt * BK_T;
        // Load K and V tiles
        for (int i = tid; i < BK_T * (HDIM / 4); i += 256) {
            const int r  = i >> 4;
            const int c4 = (i & 15) * 4;
            float4 kv = *(const float4*)&qkv[(rowbase + k0 + r) * QKVCOLS + kcol + c4];
            sK[r * QPAD + c4 + 0] = kv.x;
            sK[r * QPAD + c4 + 1] = kv.y;
            sK[r * QPAD + c4 + 2] = kv.z;
            sK[r * QPAD + c4 + 3] = kv.w;
            float4 vv = *(const float4*)&qkv[(rowbase + k0 + r) * QKVCOLS + vcol + c4];
            *(float4*)&sV[r * HDIM + c4] = vv;
        }
        __syncthreads();

        // S = Q @ K^T (each thread: 4x4 tile of the 64x64 score matrix)
        float s[4][4];
#pragma unroll
        for (int i = 0; i < 4; i++)
#pragma unroll
            for (int j = 0; j < 4; j++) s[i][j] = 0.0f;

#pragma unroll 4
        for (int kd = 0; kd < HDIM; kd++) {
            float qf[4], kf[4];
#pragma unroll
            for (int i = 0; i < 4; i++) qf[i] = sQ[(ty * 4 + i) * QPAD + kd];
#pragma unroll
            for (int j = 0; j < 4; j++) kf[j] = sK[(tx * 4 + j) * QPAD + kd];
#pragma unroll
            for (int i = 0; i < 4; i++)
#pragma unroll
                for (int j = 0; j < 4; j++)
                    s[i][j] = fmaf(qf[i], kf[j], s[i][j]);
        }

        // Scale + causal mask, write to sS
        const bool diag = (kt == n_kt - 1);
#pragma unroll
        for (int i = 0; i < 4; i++) {
            const int rg = q0 + ty * 4 + i;
#pragma unroll
            for (int j = 0; j < 4; j++) {
                const int cg = k0 + tx * 4 + j;
                float val = s[i][j] * 0.125f;          // 1/sqrt(64)
                if (diag && cg > rg) val = -1e9f;      // matches reference NEG
                sS[(ty * 4 + i) * QPAD + tx * 4 + j] = val;
            }
        }
        __syncthreads();

        // Online softmax: warp w handles rows [w*8, w*8+8)
        for (int r = warp * 8; r < warp * 8 + 8; r++) {
            float v0 = sS[r * QPAD + lane];
            float v1 = sS[r * QPAD + 32 + lane];
            float mx = fmaxf(v0, v1);
#pragma unroll
            for (int off = 16; off > 0; off >>= 1)
                mx = fmaxf(mx, __shfl_xor_sync(0xffffffffu, mx, off));
            const float mnew = fmaxf(sM[r], mx);
            const float p0 = __expf(v0 - mnew);
            const float p1 = __expf(v1 - mnew);
            sS[r * QPAD + lane] = p0;
            sS[r * QPAD + 32 + lane] = p1;
            float sum = p0 + p1;
#pragma unroll
            for (int off = 16; off > 0; off >>= 1)
                sum += __shfl_xor_sync(0xffffffffu, sum, off);
            if (lane == 0) {
                const float alpha = __expf(sM[r] - mnew);
                sA[r] = alpha;
                sL[r] = sL[r] * alpha + sum;
                sM[r] = mnew;
            }
        }
        __syncthreads();

        // O = O*alpha + P @ V
        float al[4];
#pragma unroll
        for (int i = 0; i < 4; i++) al[i] = sA[ty * 4 + i];
#pragma unroll
        for (int i = 0; i < 4; i++)
#pragma unroll
            for (int j = 0; j < 4; j++) acc[i][j] *= al[i];

#pragma unroll 4
        for (int kd = 0; kd < BK_T; kd++) {
            float pf[4], vf[4];
#pragma unroll
            for (int i = 0; i < 4; i++) pf[i] = sS[(ty * 4 + i) * QPAD + kd];
#pragma unroll
            for (int j = 0; j < 4; j++) vf[j] = sV[kd * HDIM + tx * 4 + j];
#pragma unroll
            for (int i = 0; i < 4; i++)
#pragma unroll
                for (int j = 0; j < 4; j++)
                    acc[i][j] = fmaf(pf[i], vf[j], acc[i][j]);
        }
        __syncthreads();   // protect sK/sV/sS before next tile's loads
    }

    // Normalize and store merged-head output
#pragma unroll
    for (int i = 0; i < 4; i++) {
        const int r = ty * 4 + i;
        const float inv = 1.0f / sL[r];
        float4 o;
        o.x = acc[i][0] * inv;
        o.y = acc[i][1] * inv;
        o.z = acc[i][2] * inv;
        o.w = acc[i][3] * inv;
        *(float4*)&att[(rowbase + q0 + r) * DMODEL + h * HDIM + tx * 4] = o;
    }
}

// ---------------------------------------------------------------------------
// Launch
// ---------------------------------------------------------------------------
extern "C" void kernel_launch(void* const* d_in, const int* in_sizes, int n_in,
                              void* d_out, int out_size)
{
    const float* x      = (const float*)d_in[0];  // [2,2048,1024]
    const float* W_qkv  = (const float*)d_in[1];  // [1024,3072]
    const float* b_qkv  = (const float*)d_in[2];  // [3072]
    const float* W_proj = (const float*)d_in[3];  // [1024,1024]
    const float* b_proj = (const float*)d_in[4];  // [1024]
    float* out          = (float*)d_out;          // [2,2048,1024]

    float* qkv_buf;
    float* att_buf;
    cudaGetSymbolAddress((void**)&qkv_buf, g_qkv);
    cudaGetSymbolAddress((void**)&att_buf, g_att);

    // Allow 67KB dynamic smem for the flash kernel (idempotent, capture-safe)
    cudaFuncSetAttribute(flash_attn_kernel,
                         cudaFuncAttributeMaxDynamicSharedMemorySize, SMEM_BYTES);

    // 1) QKV projection: [4096,1024] @ [1024,3072] + b
    {
        dim3 grid(QKVCOLS / 128, ROWS / 128);
        sgemm_bias_kernel<<<grid, 256>>>(x, W_qkv, b_qkv, qkv_buf,
                                         ROWS, QKVCOLS, DMODEL);
    }

    // 2) Causal flash attention over all (batch, head, q-tile)
    {
        dim3 grid(SEQ / BQ, BATCH * NHEADS);
        flash_attn_kernel<<<grid, 256, SMEM_BYTES>>>(qkv_buf, att_buf);
    }

    // 3) Output projection: [4096,1024] @ [1024,1024] + b
    {
        dim3 grid(DMODEL / 128, ROWS / 128);
        sgemm_bias_kernel<<<grid, 256>>>(att_buf, W_proj, b_proj, out,
                                         ROWS, DMODEL, DMODEL);
    }
}

// round 3
// speedup vs baseline: 2.3650x; 2.3650x over previous
#include <cuda_runtime.h>
#include <math.h>

// Problem constants (fixed by the reference)
#define BATCH   2
#define SEQ     2048
#define DMODEL  1024
#define NHEADS  16
#define HDIM    64
#define ROWS    (BATCH * SEQ)        // 4096
#define QKVCOLS (3 * DMODEL)         // 3072

// Scratch (static device globals — allocation-free per harness rules)
__device__ float g_qkv[(size_t)ROWS * QKVCOLS];   // 50 MB
__device__ float g_att[(size_t)ROWS * DMODEL];    // 16 MB

// ---------------------------------------------------------------------------
// Helpers
// ---------------------------------------------------------------------------
__device__ __forceinline__ unsigned f2tf32(float x) {
    unsigned r;
    asm("cvt.rna.tf32.f32 %0, %1;" : "=r"(r) : "f"(x));
    return r;
}

// D += A(16x8) * B(8x8), tf32 inputs, fp32 accumulate
#define MMA_TF32(d, a, b)                                                     \
    asm volatile(                                                             \
        "mma.sync.aligned.m16n8k8.row.col.f32.tf32.tf32.f32 "                 \
        "{%0,%1,%2,%3},{%4,%5,%6,%7},{%8,%9},{%0,%1,%2,%3};"                  \
        : "+f"((d)[0]), "+f"((d)[1]), "+f"((d)[2]), "+f"((d)[3])              \
        : "r"((a)[0]), "r"((a)[1]), "r"((a)[2]), "r"((a)[3]),                 \
          "r"((b)[0]), "r"((b)[1]))

// ---------------------------------------------------------------------------
// TF32 tensor-core GEMM: C[M,N] = A[M,K] @ B[K,N] + bias[N]
// Block 128x128, BK=32, 256 threads (8 warps in 4x2 grid, warp tile 32x64).
// As[m][k] pad 36 (36%32==4 -> a-frag bank = lane, conflict-free)
// Bs[k][n] pad 136 (136%32==8 -> b-frag bank = 8*k4+n8, conflict-free)
// ---------------------------------------------------------------------------
__global__ __launch_bounds__(256)
void gemm_tf32_kernel(const float* __restrict__ A,
                      const float* __restrict__ Bm,
                      const float* __restrict__ bias,
                      float* __restrict__ C,
                      int M, int N, int K)
{
    __shared__ unsigned As[128][36];
    __shared__ unsigned Bs[32][136];

    const int tid  = threadIdx.x;
    const int lane = tid & 31;
    const int warp = tid >> 5;
    const int g    = lane >> 2;          // 0..7
    const int t4   = lane & 3;           // 0..3
    const int wm   = (warp >> 1) * 32;   // warp row offset in block tile
    const int wn   = (warp & 1) * 64;    // warp col offset
    const int row0 = blockIdx.y * 128;
    const int col0 = blockIdx.x * 128;

    float acc[2][8][4];
#pragma unroll
    for (int mt = 0; mt < 2; mt++)
#pragma unroll
        for (int nt = 0; nt < 8; nt++)
#pragma unroll
            for (int c = 0; c < 4; c++) acc[mt][nt][c] = 0.0f;

    // Loader coordinates
    const int ar = tid >> 3;             // 0..31 (A row, 4 passes of +32)
    const int ak = (tid & 7) * 4;        // A k-col
    const int bk = tid >> 5;             // 0..7  (B k-row, 4 passes of +8)
    const int bn = (tid & 31) * 4;       // B n-col

    const float* Ap = A + (size_t)(row0 + ar) * K + ak;
    const float* Bp = Bm + (size_t)bk * N + col0 + bn;

    // Preload first K-tile into registers
    float4 stA[4], stB[4];
#pragma unroll
    for (int p = 0; p < 4; p++) {
        stA[p] = *(const float4*)(Ap + (size_t)(p * 32) * K);
        stB[p] = *(const float4*)(Bp + (size_t)(p * 8) * N);
    }

    for (int k0 = 0; k0 < K; k0 += 32) {
        // Commit staged tile to shared (with tf32 conversion)
#pragma unroll
        for (int p = 0; p < 4; p++) {
            unsigned* d = &As[ar + p * 32][ak];
            d[0] = f2tf32(stA[p].x); d[1] = f2tf32(stA[p].y);
            d[2] = f2tf32(stA[p].z); d[3] = f2tf32(stA[p].w);
            unsigned* e = &Bs[bk + p * 8][bn];
            e[0] = f2tf32(stB[p].x); e[1] = f2tf32(stB[p].y);
            e[2] = f2tf32(stB[p].z); e[3] = f2tf32(stB[p].w);
        }
        __syncthreads();

        // Prefetch next K-tile (overlaps the mma loop)
        const int k1 = k0 + 32;
        if (k1 < K) {
#pragma unroll
            for (int p = 0; p < 4; p++) {
                stA[p] = *(const float4*)(Ap + k1 + (size_t)(p * 32) * K);
                stB[p] = *(const float4*)(Bp + (size_t)(k1 + p * 8) * N);
            }
        }

#pragma unroll
        for (int ks = 0; ks < 4; ks++) {
            const int k8 = ks * 8;
            unsigned af[2][4];
#pragma unroll
            for (int mt = 0; mt < 2; mt++) {
                const int r = wm + mt * 16;
                af[mt][0] = As[r + g][k8 + t4];
                af[mt][1] = As[r + g + 8][k8 + t4];
                af[mt][2] = As[r + g][k8 + t4 + 4];
                af[mt][3] = As[r + g + 8][k8 + t4 + 4];
            }
            unsigned bf[8][2];
#pragma unroll
            for (int nt = 0; nt < 8; nt++) {
                const int c = wn + nt * 8 + g;
                bf[nt][0] = Bs[k8 + t4][c];
                bf[nt][1] = Bs[k8 + t4 + 4][c];
            }
#pragma unroll
            for (int mt = 0; mt < 2; mt++)
#pragma unroll
                for (int nt = 0; nt < 8; nt++)
                    MMA_TF32(acc[mt][nt], af[mt], bf[nt]);
        }
        __syncthreads();
    }

    // Epilogue: bias + float2 stores
#pragma unroll
    for (int mt = 0; mt < 2; mt++) {
        const int rA = row0 + wm + mt * 16 + g;
#pragma unroll
        for (int nt = 0; nt < 8; nt++) {
            const int c = col0 + wn + nt * 8 + 2 * t4;
            const float2 bv = *(const float2*)&bias[c];
            float2 o0, o1;
            o0.x = acc[mt][nt][0] + bv.x;
            o0.y = acc[mt][nt][1] + bv.y;
            o1.x = acc[mt][nt][2] + bv.x;
            o1.y = acc[mt][nt][3] + bv.y;
            *(float2*)&C[(size_t)rA * N + c] = o0;
            *(float2*)&C[(size_t)(rA + 8) * N + c] = o1;
        }
    }
}

// ---------------------------------------------------------------------------
// Flash attention, TF32 tensor-core QK^T and PV, fp32 online softmax.
// 64 q-rows/block, 64-key tiles. 8 warps in 4x2 grid over the 64x64 tiles.
// sQ[64][68], sK[64][68] tf32; sS[64][68] fp32 scores -> tf32 probs;
// sV[64][72] tf32. Pads: 68%32==4 (a/b-frag bank=lane), 72%32==8.
// ---------------------------------------------------------------------------
#define SMEM_ATT_FLOATS (3 * 64 * 68 + 64 * 72 + 3 * 64)
#define SMEM_ATT_BYTES  (SMEM_ATT_FLOATS * 4)

__global__ __launch_bounds__(256, 2)
void flash_attn_tf32_kernel(const float* __restrict__ qkv,
                            float* __restrict__ att)
{
    extern __shared__ float smf[];
    unsigned* sQ = (unsigned*)smf;            // [64][68]
    unsigned* sK = sQ + 64 * 68;              // [64][68]
    float*    sS = (float*)(sK + 64 * 68);    // [64][68]
    unsigned* sV = (unsigned*)(sS + 64 * 68); // [64][72]
    float* sM = (float*)(sV + 64 * 72);       // [64]
    float* sL = sM + 64;                      // [64]
    float* sA = sL + 64;                      // [64]

    const int tid  = threadIdx.x;
    const int lane = tid & 31;
    const int warp = tid >> 5;
    const int g    = lane >> 2;
    const int t4   = lane & 3;
    const int rb   = (warp >> 1) * 16;        // warp rows in 64x64 tile
    const int cb   = (warp & 1) * 32;         // warp cols

    const int bh = blockIdx.y;
    const int b  = bh / NHEADS;
    const int h  = bh % NHEADS;
    const int qt = gridDim.x - 1 - blockIdx.x;   // heavy tiles first
    const int q0 = qt * 64;

    const size_t rowbase = (size_t)b * SEQ;
    const int qcol = h * HDIM;
    const int kcol = DMODEL + h * HDIM;
    const int vcol = 2 * DMODEL + h * HDIM;

    // Load Q tile (tf32 convert once)
    for (int i = tid; i < 64 * 16; i += 256) {
        const int r  = i >> 4;
        const int c4 = (i & 15) * 4;
        float4 v = *(const float4*)&qkv[(rowbase + q0 + r) * QKVCOLS + qcol + c4];
        unsigned* d = &sQ[r * 68 + c4];
        d[0] = f2tf32(v.x); d[1] = f2tf32(v.y);
        d[2] = f2tf32(v.z); d[3] = f2tf32(v.w);
    }
    if (tid < 64) { sM[tid] = -1e30f; sL[tid] = 0.0f; }

    float o[4][4];
#pragma unroll
    for (int nt = 0; nt < 4; nt++)
#pragma unroll
        for (int c = 0; c < 4; c++) o[nt][c] = 0.0f;

    __syncthreads();

    const int n_kt = q0 / 64 + 1;
    for (int kt = 0; kt < n_kt; kt++) {
        const int k0 = kt * 64;
        // Load K, V tiles (tf32 convert)
        for (int i = tid; i < 64 * 16; i += 256) {
            const int r  = i >> 4;
            const int c4 = (i & 15) * 4;
            float4 kv = *(const float4*)&qkv[(rowbase + k0 + r) * QKVCOLS + kcol + c4];
            unsigned* dk = &sK[r * 68 + c4];
            dk[0] = f2tf32(kv.x); dk[1] = f2tf32(kv.y);
            dk[2] = f2tf32(kv.z); dk[3] = f2tf32(kv.w);
            float4 vv = *(const float4*)&qkv[(rowbase + k0 + r) * QKVCOLS + vcol + c4];
            unsigned* dv = &sV[r * 72 + c4];
            dv[0] = f2tf32(vv.x); dv[1] = f2tf32(vv.y);
            dv[2] = f2tf32(vv.z); dv[3] = f2tf32(vv.w);
        }
        __syncthreads();

        // S = Q @ K^T via mma (each warp: 16x32 slice as 4 n-tiles)
        float s[4][4];
#pragma unroll
        for (int nt = 0; nt < 4; nt++)
#pragma unroll
            for (int c = 0; c < 4; c++) s[nt][c] = 0.0f;

#pragma unroll
        for (int ks = 0; ks < 8; ks++) {
            const int k8 = ks * 8;
            unsigned a[4];
            a[0] = sQ[(rb + g) * 68 + k8 + t4];
            a[1] = sQ[(rb + g + 8) * 68 + k8 + t4];
            a[2] = sQ[(rb + g) * 68 + k8 + t4 + 4];
            a[3] = sQ[(rb + g + 8) * 68 + k8 + t4 + 4];
#pragma unroll
            for (int nt = 0; nt < 4; nt++) {
                const int cc = cb + nt * 8 + g;
                unsigned bfr[2];
                bfr[0] = sK[cc * 68 + k8 + t4];
                bfr[1] = sK[cc * 68 + k8 + t4 + 4];
                MMA_TF32(s[nt], a, bfr);
            }
        }

        // Scale + causal mask, write scores to sS (fp32)
        const bool diag = (kt == n_kt - 1);
        const int rgA = q0 + rb + g;
        const int rgB = rgA + 8;
#pragma unroll
        for (int nt = 0; nt < 4; nt++) {
            const int cg = k0 + cb + nt * 8 + 2 * t4;
            float v0 = s[nt][0] * 0.125f;
            float v1 = s[nt][1] * 0.125f;
            float v2 = s[nt][2] * 0.125f;
            float v3 = s[nt][3] * 0.125f;
            if (diag) {
                if (cg > rgA)     v0 = -1e9f;
                if (cg + 1 > rgA) v1 = -1e9f;
                if (cg > rgB)     v2 = -1e9f;
                if (cg + 1 > rgB) v3 = -1e9f;
            }
            const int so = cb + nt * 8 + 2 * t4;
            sS[(rb + g) * 68 + so]     = v0;
            sS[(rb + g) * 68 + so + 1] = v1;
            sS[(rb + g + 8) * 68 + so]     = v2;
            sS[(rb + g + 8) * 68 + so + 1] = v3;
        }
        __syncthreads();

        // Online softmax: warp w handles rows [w*8, w*8+8); probs stored tf32
        for (int r = warp * 8; r < warp * 8 + 8; r++) {
            float v0 = sS[r * 68 + lane];
            float v1 = sS[r * 68 + 32 + lane];
            float mx = fmaxf(v0, v1);
#pragma unroll
            for (int off = 16; off > 0; off >>= 1)
                mx = fmaxf(mx, __shfl_xor_sync(0xffffffffu, mx, off));
            const float mnew = fmaxf(sM[r], mx);
            const float p0 = __expf(v0 - mnew);
            const float p1 = __expf(v1 - mnew);
            sS[r * 68 + lane]      = __uint_as_float(f2tf32(p0));
            sS[r * 68 + 32 + lane] = __uint_as_float(f2tf32(p1));
            float sum = p0 + p1;
#pragma unroll
            for (int off = 16; off > 0; off >>= 1)
                sum += __shfl_xor_sync(0xffffffffu, sum, off);
            if (lane == 0) {
                const float alpha = __expf(sM[r] - mnew);
                sA[r] = alpha;
                sL[r] = sL[r] * alpha + sum;
                sM[r] = mnew;
            }
        }
        __syncthreads();

        // O = O*alpha + P @ V via mma
        const float alA = sA[rb + g];
        const float alB = sA[rb + g + 8];
#pragma unroll
        for (int nt = 0; nt < 4; nt++) {
            o[nt][0] *= alA; o[nt][1] *= alA;
            o[nt][2] *= alB; o[nt][3] *= alB;
        }
#pragma unroll
        for (int ks = 0; ks < 8; ks++) {
            const int k8 = ks * 8;
            unsigned a[4];
            a[0] = __float_as_uint(sS[(rb + g) * 68 + k8 + t4]);
            a[1] = __float_as_uint(sS[(rb + g + 8) * 68 + k8 + t4]);
            a[2] = __float_as_uint(sS[(rb + g) * 68 + k8 + t4 + 4]);
            a[3] = __float_as_uint(sS[(rb + g + 8) * 68 + k8 + t4 + 4]);
#pragma unroll
            for (int nt = 0; nt < 4; nt++) {
                const int cc = cb + nt * 8 + g;
                unsigned bfr[2];
                bfr[0] = sV[(k8 + t4) * 72 + cc];
                bfr[1] = sV[(k8 + t4 + 4) * 72 + cc];
                MMA_TF32(o[nt], a, bfr);
            }
        }
        __syncthreads();   // protect sK/sV/sS before next tile's loads
    }

    // Normalize and store merged-head output (float2 per tile-row)
    const float invA = 1.0f / sL[rb + g];
    const float invB = 1.0f / sL[rb + g + 8];
    const size_t rA = rowbase + q0 + rb + g;
#pragma unroll
    for (int nt = 0; nt < 4; nt++) {
        const int col = h * HDIM + cb + nt * 8 + 2 * t4;
        float2 o0, o1;
        o0.x = o[nt][0] * invA; o0.y = o[nt][1] * invA;
        o1.x = o[nt][2] * invB; o1.y = o[nt][3] * invB;
        *(float2*)&att[rA * DMODEL + col] = o0;
        *(float2*)&att[(rA + 8) * DMODEL + col] = o1;
    }
}

// ---------------------------------------------------------------------------
// Launch
// ---------------------------------------------------------------------------
extern "C" void kernel_launch(void* const* d_in, const int* in_sizes, int n_in,
                              void* d_out, int out_size)
{
    const float* x      = (const float*)d_in[0];  // [2,2048,1024]
    const float* W_qkv  = (const float*)d_in[1];  // [1024,3072]
    const float* b_qkv  = (const float*)d_in[2];  // [3072]
    const float* W_proj = (const float*)d_in[3];  // [1024,1024]
    const float* b_proj = (const float*)d_in[4];  // [1024]
    float* out          = (float*)d_out;          // [2,2048,1024]

    float* qkv_buf;
    float* att_buf;
    cudaGetSymbolAddress((void**)&qkv_buf, g_qkv);
    cudaGetSymbolAddress((void**)&att_buf, g_att);

    cudaFuncSetAttribute(flash_attn_tf32_kernel,
                         cudaFuncAttributeMaxDynamicSharedMemorySize,
                         SMEM_ATT_BYTES);

    // 1) QKV projection: [4096,1024] @ [1024,3072] + b
    {
        dim3 grid(QKVCOLS / 128, ROWS / 128);
        gemm_tf32_kernel<<<grid, 256>>>(x, W_qkv, b_qkv, qkv_buf,
                                        ROWS, QKVCOLS, DMODEL);
    }

    // 2) Causal flash attention over all (batch, head, q-tile)
    {
        dim3 grid(SEQ / 64, BATCH * NHEADS);
        flash_attn_tf32_kernel<<<grid, 256, SMEM_ATT_BYTES>>>(qkv_buf, att_buf);
    }

    // 3) Output projection: [4096,1024] @ [1024,1024] + b
    {
        dim3 grid(DMODEL / 128, ROWS / 128);
        gemm_tf32_kernel<<<grid, 256>>>(att_buf, W_proj, b_proj, out,
                                        ROWS, DMODEL, DMODEL);
    }
}

// round 4
// speedup vs baseline: 3.3368x; 1.4109x over previous
#include <cuda_runtime.h>
#include <math.h>

// Problem constants (fixed by the reference)
#define BATCH   2
#define SEQ     2048
#define DMODEL  1024
#define NHEADS  16
#define HDIM    64
#define ROWS    (BATCH * SEQ)        // 4096
#define QKVCOLS (3 * DMODEL)         // 3072

// Scratch (static device globals — allocation-free per harness rules)
__device__ float g_qkv[(size_t)ROWS * QKVCOLS];   // 50 MB
__device__ float g_att[(size_t)ROWS * DMODEL];    // 16 MB

// ---------------------------------------------------------------------------
// Helpers
// ---------------------------------------------------------------------------
__device__ __forceinline__ unsigned f2tf32(float x) {
    unsigned r;
    asm("cvt.rna.tf32.f32 %0, %1;" : "=r"(r) : "f"(x));
    return r;
}

// D += A(16x8) * B(8x8), tf32 inputs, fp32 accumulate
#define MMA_TF32(d, a, b)                                                     \
    asm volatile(                                                             \
        "mma.sync.aligned.m16n8k8.row.col.f32.tf32.tf32.f32 "                 \
        "{%0,%1,%2,%3},{%4,%5,%6,%7},{%8,%9},{%0,%1,%2,%3};"                  \
        : "+f"((d)[0]), "+f"((d)[1]), "+f"((d)[2]), "+f"((d)[3])              \
        : "r"((a)[0]), "r"((a)[1]), "r"((a)[2]), "r"((a)[3]),                 \
          "r"((b)[0]), "r"((b)[1]))

// ---------------------------------------------------------------------------
// TF32 tensor-core GEMM: C[M,N] = A[M,K] @ B[K,N] + bias[N]
// Block 128x128, BK=32, 256 threads (8 warps, warp tile 32x64).
// Double-buffered smem, ONE __syncthreads per K-tile:
//   LDG(next) -> mma(cur) -> cvt+STS(next buffer) -> sync -> swap
// As pad 36 (36%32==4 -> a-frag bank = lane), Bs pad 136 (136%32==8).
// Dynamic smem: 2*(128*36 + 32*136)*4 = 71680 B.
// ---------------------------------------------------------------------------
#define GEMM_SMEM_BYTES (2 * (128 * 36 + 32 * 136) * 4)

__global__ __launch_bounds__(256)
void gemm_tf32_kernel(const float* __restrict__ A,
                      const float* __restrict__ Bm,
                      const float* __restrict__ bias,
                      float* __restrict__ C,
                      int M, int N, int K)
{
    extern __shared__ unsigned gsm[];
    unsigned* As = gsm;                       // [2][128][36]
    unsigned* Bs = gsm + 2 * 128 * 36;        // [2][32][136]

    const int tid  = threadIdx.x;
    const int lane = tid & 31;
    const int warp = tid >> 5;
    const int g    = lane >> 2;          // 0..7
    const int t4   = lane & 3;           // 0..3
    const int wm   = (warp >> 1) * 32;   // warp row offset in block tile
    const int wn   = (warp & 1) * 64;    // warp col offset
    const int row0 = blockIdx.y * 128;
    const int col0 = blockIdx.x * 128;

    float acc[2][8][4];
#pragma unroll
    for (int mt = 0; mt < 2; mt++)
#pragma unroll
        for (int nt = 0; nt < 8; nt++)
#pragma unroll
            for (int c = 0; c < 4; c++) acc[mt][nt][c] = 0.0f;

    // Loader coordinates
    const int ar = tid >> 3;             // 0..31 (A row, 4 passes of +32)
    const int ak = (tid & 7) * 4;        // A k-col
    const int bk = tid >> 5;             // 0..7  (B k-row, 4 passes of +8)
    const int bn = (tid & 31) * 4;       // B n-col

    const float* Ap = A + (size_t)(row0 + ar) * K + ak;
    const float* Bp = Bm + (size_t)bk * N + col0 + bn;

    // Load first tile into buffer 0
    {
        float4 stA[4], stB[4];
#pragma unroll
        for (int p = 0; p < 4; p++) {
            stA[p] = *(const float4*)(Ap + (size_t)(p * 32) * K);
            stB[p] = *(const float4*)(Bp + (size_t)(p * 8) * N);
        }
#pragma unroll
        for (int p = 0; p < 4; p++) {
            unsigned* d = &As[(ar + p * 32) * 36 + ak];
            d[0] = f2tf32(stA[p].x); d[1] = f2tf32(stA[p].y);
            d[2] = f2tf32(stA[p].z); d[3] = f2tf32(stA[p].w);
            unsigned* e = &Bs[(bk + p * 8) * 136 + bn];
            e[0] = f2tf32(stB[p].x); e[1] = f2tf32(stB[p].y);
            e[2] = f2tf32(stB[p].z); e[3] = f2tf32(stB[p].w);
        }
    }
    __syncthreads();

    int cur = 0;
    for (int k0 = 0; k0 < K; k0 += 32) {
        const int k1 = k0 + 32;
        float4 stA[4], stB[4];
        if (k1 < K) {
#pragma unroll
            for (int p = 0; p < 4; p++) {
                stA[p] = *(const float4*)(Ap + k1 + (size_t)(p * 32) * K);
                stB[p] = *(const float4*)(Bp + (size_t)(k1 + p * 8) * N);
            }
        }

        const unsigned* Ac = As + cur * 128 * 36;
        const unsigned* Bc = Bs + cur * 32 * 136;
#pragma unroll
        for (int ks = 0; ks < 4; ks++) {
            const int k8 = ks * 8;
            unsigned af[2][4];
#pragma unroll
            for (int mt = 0; mt < 2; mt++) {
                const int r = wm + mt * 16;
                af[mt][0] = Ac[(r + g) * 36 + k8 + t4];
                af[mt][1] = Ac[(r + g + 8) * 36 + k8 + t4];
                af[mt][2] = Ac[(r + g) * 36 + k8 + t4 + 4];
                af[mt][3] = Ac[(r + g + 8) * 36 + k8 + t4 + 4];
            }
            unsigned bf[8][2];
#pragma unroll
            for (int nt = 0; nt < 8; nt++) {
                const int c = wn + nt * 8 + g;
                bf[nt][0] = Bc[(k8 + t4) * 136 + c];
                bf[nt][1] = Bc[(k8 + t4 + 4) * 136 + c];
            }
#pragma unroll
            for (int mt = 0; mt < 2; mt++)
#pragma unroll
                for (int nt = 0; nt < 8; nt++)
                    MMA_TF32(acc[mt][nt], af[mt], bf[nt]);
        }

        if (k1 < K) {
            unsigned* An = As + (cur ^ 1) * 128 * 36;
            unsigned* Bn = Bs + (cur ^ 1) * 32 * 136;
#pragma unroll
            for (int p = 0; p < 4; p++) {
                unsigned* d = &An[(ar + p * 32) * 36 + ak];
                d[0] = f2tf32(stA[p].x); d[1] = f2tf32(stA[p].y);
                d[2] = f2tf32(stA[p].z); d[3] = f2tf32(stA[p].w);
                unsigned* e = &Bn[(bk + p * 8) * 136 + bn];
                e[0] = f2tf32(stB[p].x); e[1] = f2tf32(stB[p].y);
                e[2] = f2tf32(stB[p].z); e[3] = f2tf32(stB[p].w);
            }
        }
        __syncthreads();
        cur ^= 1;
    }

    // Epilogue: bias + float2 stores
#pragma unroll
    for (int mt = 0; mt < 2; mt++) {
        const int rA = row0 + wm + mt * 16 + g;
#pragma unroll
        for (int nt = 0; nt < 8; nt++) {
            const int c = col0 + wn + nt * 8 + 2 * t4;
            const float2 bv = *(const float2*)&bias[c];
            float2 o0, o1;
            o0.x = acc[mt][nt][0] + bv.x;
            o0.y = acc[mt][nt][1] + bv.y;
            o1.x = acc[mt][nt][2] + bv.x;
            o1.y = acc[mt][nt][3] + bv.y;
            *(float2*)&C[(size_t)rA * N + c] = o0;
            *(float2*)&C[(size_t)(rA + 8) * N + c] = o1;
        }
    }
}

// ---------------------------------------------------------------------------
// Flash attention v2-style: BQ=128 q-rows/block, BK=64 keys/tile, 8 warps.
// Warp w owns rows [16w,16w+16): softmax entirely in registers (quad shfl),
// Q persistent in registers (a-frags), P staged through warp-private smem
// rows. One __syncthreads per k-tile.
//   sK[64][68] tf32, sV[64][72] tf32, sP[128][68] tf32 (also Q staging)
// ---------------------------------------------------------------------------
#define SMEM_ATT_BYTES ((64 * 68 + 64 * 72 + 128 * 68) * 4)

__global__ __launch_bounds__(256)
void flash_attn_tf32_kernel(const float* __restrict__ qkv,
                            float* __restrict__ att)
{
    extern __shared__ unsigned asm_[];
    unsigned* sK = asm_;                 // [64][68]
    unsigned* sV = sK + 64 * 68;         // [64][72]
    unsigned* sP = sV + 64 * 72;         // [128][68]  (Q staging, then P)

    const int tid  = threadIdx.x;
    const int lane = tid & 31;
    const int warp = tid >> 5;           // 0..7 -> rows [16w,16w+16)
    const int g    = lane >> 2;          // 0..7
    const int t4   = lane & 3;           // 0..3
    const int wr   = warp * 16;          // warp row base in q-tile

    const int bh = blockIdx.y;
    const int b  = bh / NHEADS;
    const int h  = bh % NHEADS;
    const int qt = gridDim.x - 1 - blockIdx.x;   // heavy tiles first
    const int q0 = qt * 128;

    const size_t rowbase = (size_t)b * SEQ;
    const int qcol = h * HDIM;
    const int kcol = DMODEL + h * HDIM;
    const int vcol = 2 * DMODEL + h * HDIM;

    // ---- Stage Q tile (coalesced) into sP, convert tf32 ----
    for (int i = tid; i < 128 * 16; i += 256) {
        const int r  = i >> 4;
        const int c4 = (i & 15) * 4;
        float4 v = *(const float4*)&qkv[(rowbase + q0 + r) * QKVCOLS + qcol + c4];
        unsigned* d = &sP[r * 68 + c4];
        d[0] = f2tf32(v.x); d[1] = f2tf32(v.y);
        d[2] = f2tf32(v.z); d[3] = f2tf32(v.w);
    }
    __syncthreads();

    // Q a-frags: qf[ks] covers k-cols [8ks,8ks+8)
    unsigned qf[8][4];
#pragma unroll
    for (int ks = 0; ks < 8; ks++) {
        const int k8 = ks * 8;
        qf[ks][0] = sP[(wr + g) * 68 + k8 + t4];
        qf[ks][1] = sP[(wr + g + 8) * 68 + k8 + t4];
        qf[ks][2] = sP[(wr + g) * 68 + k8 + t4 + 4];
        qf[ks][3] = sP[(wr + g + 8) * 68 + k8 + t4 + 4];
    }

    // Row stats (rows wr+g and wr+g+8) and output accum
    float m0 = -1e30f, m1 = -1e30f, l0 = 0.0f, l1 = 0.0f;
    float o[8][4];
#pragma unroll
    for (int nt = 0; nt < 8; nt++)
#pragma unroll
        for (int c = 0; c < 4; c++) o[nt][c] = 0.0f;

    const int n_kt = 2 * qt + 2;
    for (int kt = 0; kt < n_kt; kt++) {
        const int k0 = kt * 64;
        // ---- Load K, V tiles (tf32) ----
        for (int i = tid; i < 64 * 16; i += 256) {
            const int r  = i >> 4;
            const int c4 = (i & 15) * 4;
            float4 kv = *(const float4*)&qkv[(rowbase + k0 + r) * QKVCOLS + kcol + c4];
            unsigned* dk = &sK[r * 68 + c4];
            dk[0] = f2tf32(kv.x); dk[1] = f2tf32(kv.y);
            dk[2] = f2tf32(kv.z); dk[3] = f2tf32(kv.w);
            float4 vv = *(const float4*)&qkv[(rowbase + k0 + r) * QKVCOLS + vcol + c4];
            unsigned* dv = &sV[r * 72 + c4];
            dv[0] = f2tf32(vv.x); dv[1] = f2tf32(vv.y);
            dv[2] = f2tf32(vv.z); dv[3] = f2tf32(vv.w);
        }
        __syncthreads();

        // Per-warp causal early-out: warp fully masked if max row < min key
        if (q0 + wr + 15 >= k0) {
            // ---- S = Q @ K^T : warp computes 16x64 in registers ----
            float s[8][4];
#pragma unroll
            for (int nt = 0; nt < 8; nt++)
#pragma unroll
                for (int c = 0; c < 4; c++) s[nt][c] = 0.0f;
#pragma unroll
            for (int ks = 0; ks < 8; ks++) {
                const int k8 = ks * 8;
#pragma unroll
                for (int nt = 0; nt < 8; nt++) {
                    const int cc = nt * 8 + g;
                    unsigned bfr[2];
                    bfr[0] = sK[cc * 68 + k8 + t4];
                    bfr[1] = sK[cc * 68 + k8 + t4 + 4];
                    MMA_TF32(s[nt], qf[ks], bfr);
                }
            }

            // ---- Scale + causal mask (register-level) ----
            const bool diag = (kt >= 2 * qt);
            const int rg0 = q0 + wr + g;
            const int rg1 = rg0 + 8;
#pragma unroll
            for (int nt = 0; nt < 8; nt++) {
                const int cg = k0 + nt * 8 + 2 * t4;
                s[nt][0] *= 0.125f; s[nt][1] *= 0.125f;
                s[nt][2] *= 0.125f; s[nt][3] *= 0.125f;
                if (diag) {
                    if (cg > rg0)     s[nt][0] = -1e9f;
                    if (cg + 1 > rg0) s[nt][1] = -1e9f;
                    if (cg > rg1)     s[nt][2] = -1e9f;
                    if (cg + 1 > rg1) s[nt][3] = -1e9f;
                }
            }

            // ---- Online softmax in registers (quad reduction) ----
            float mx0 = -1e30f, mx1 = -1e30f;
#pragma unroll
            for (int nt = 0; nt < 8; nt++) {
                mx0 = fmaxf(mx0, fmaxf(s[nt][0], s[nt][1]));
                mx1 = fmaxf(mx1, fmaxf(s[nt][2], s[nt][3]));
            }
            mx0 = fmaxf(mx0, __shfl_xor_sync(0xffffffffu, mx0, 1));
            mx0 = fmaxf(mx0, __shfl_xor_sync(0xffffffffu, mx0, 2));
            mx1 = fmaxf(mx1, __shfl_xor_sync(0xffffffffu, mx1, 1));
            mx1 = fmaxf(mx1, __shfl_xor_sync(0xffffffffu, mx1, 2));

            const float m0n = fmaxf(m0, mx0);
            const float m1n = fmaxf(m1, mx1);
            const float al0 = __expf(m0 - m0n);
            const float al1 = __expf(m1 - m1n);

            float sum0 = 0.0f, sum1 = 0.0f;
#pragma unroll
            for (int nt = 0; nt < 8; nt++) {
                s[nt][0] = __expf(s[nt][0] - m0n);
                s[nt][1] = __expf(s[nt][1] - m0n);
                s[nt][2] = __expf(s[nt][2] - m1n);
                s[nt][3] = __expf(s[nt][3] - m1n);
                sum0 += s[nt][0] + s[nt][1];
                sum1 += s[nt][2] + s[nt][3];
            }
            sum0 += __shfl_xor_sync(0xffffffffu, sum0, 1);
            sum0 += __shfl_xor_sync(0xffffffffu, sum0, 2);
            sum1 += __shfl_xor_sync(0xffffffffu, sum1, 1);
            sum1 += __shfl_xor_sync(0xffffffffu, sum1, 2);

            l0 = l0 * al0 + sum0;
            l1 = l1 * al1 + sum1;
            m0 = m0n; m1 = m1n;

            // Rescale output accumulators
#pragma unroll
            for (int nt = 0; nt < 8; nt++) {
                o[nt][0] *= al0; o[nt][1] *= al0;
                o[nt][2] *= al1; o[nt][3] *= al1;
            }

            // ---- Stage P (tf32) in warp-private sP rows ----
#pragma unroll
            for (int nt = 0; nt < 8; nt++) {
                const int c2 = nt * 8 + 2 * t4;
                sP[(wr + g) * 68 + c2]     = f2tf32(s[nt][0]);
                sP[(wr + g) * 68 + c2 + 1] = f2tf32(s[nt][1]);
                sP[(wr + g + 8) * 68 + c2]     = f2tf32(s[nt][2]);
                sP[(wr + g + 8) * 68 + c2 + 1] = f2tf32(s[nt][3]);
            }
            __syncwarp();

            // ---- O += P @ V ----
#pragma unroll
            for (int ks = 0; ks < 8; ks++) {
                const int k8 = ks * 8;
                unsigned a[4];
                a[0] = sP[(wr + g) * 68 + k8 + t4];
                a[1] = sP[(wr + g + 8) * 68 + k8 + t4];
                a[2] = sP[(wr + g) * 68 + k8 + t4 + 4];
                a[3] = sP[(wr + g + 8) * 68 + k8 + t4 + 4];
#pragma unroll
                for (int nt = 0; nt < 8; nt++) {
                    const int cc = nt * 8 + g;
                    unsigned bfr[2];
                    bfr[0] = sV[(k8 + t4) * 72 + cc];
                    bfr[1] = sV[(k8 + t4 + 4) * 72 + cc];
                    MMA_TF32(o[nt], a, bfr);
                }
            }
        }
        __syncthreads();   // protect sK/sV before next tile's loads
    }

    // ---- Normalize and store merged-head output ----
    const float inv0 = 1.0f / l0;
    const float inv1 = 1.0f / l1;
    const size_t r0 = rowbase + q0 + wr + g;
#pragma unroll
    for (int nt = 0; nt < 8; nt++) {
        const int col = h * HDIM + nt * 8 + 2 * t4;
        float2 v0, v1;
        v0.x = o[nt][0] * inv0; v0.y = o[nt][1] * inv0;
        v1.x = o[nt][2] * inv1; v1.y = o[nt][3] * inv1;
        *(float2*)&att[r0 * DMODEL + col] = v0;
        *(float2*)&att[(r0 + 8) * DMODEL + col] = v1;
    }
}

// ---------------------------------------------------------------------------
// Launch
// ---------------------------------------------------------------------------
extern "C" void kernel_launch(void* const* d_in, const int* in_sizes, int n_in,
                              void* d_out, int out_size)
{
    const float* x      = (const float*)d_in[0];  // [2,2048,1024]
    const float* W_qkv  = (const float*)d_in[1];  // [1024,3072]
    const float* b_qkv  = (const float*)d_in[2];  // [3072]
    const float* W_proj = (const float*)d_in[3];  // [1024,1024]
    const float* b_proj = (const float*)d_in[4];  // [1024]
    float* out          = (float*)d_out;          // [2,2048,1024]

    float* qkv_buf;
    float* att_buf;
    cudaGetSymbolAddress((void**)&qkv_buf, g_qkv);
    cudaGetSymbolAddress((void**)&att_buf, g_att);

    cudaFuncSetAttribute(gemm_tf32_kernel,
                         cudaFuncAttributeMaxDynamicSharedMemorySize,
                         GEMM_SMEM_BYTES);
    cudaFuncSetAttribute(flash_attn_tf32_kernel,
                         cudaFuncAttributeMaxDynamicSharedMemorySize,
                         SMEM_ATT_BYTES);

    // 1) QKV projection: [4096,1024] @ [1024,3072] + b
    {
        dim3 grid(QKVCOLS / 128, ROWS / 128);
        gemm_tf32_kernel<<<grid, 256, GEMM_SMEM_BYTES>>>(
            x, W_qkv, b_qkv, qkv_buf, ROWS, QKVCOLS, DMODEL);
    }

    // 2) Causal flash attention over all (batch, head, q-tile)
    {
        dim3 grid(SEQ / 128, BATCH * NHEADS);
        flash_attn_tf32_kernel<<<grid, 256, SMEM_ATT_BYTES>>>(qkv_buf, att_buf);
    }

    // 3) Output projection: [4096,1024] @ [1024,1024] + b
    {
        dim3 grid(DMODEL / 128, ROWS / 128);
        gemm_tf32_kernel<<<grid, 256, GEMM_SMEM_BYTES>>>(
            att_buf, W_proj, b_proj, out, ROWS, DMODEL, DMODEL);
    }
}